// round 3
// baseline (speedup 1.0000x reference)
#include <cuda_runtime.h>
#include <math.h>

#define B_    64
#define T_    2048
#define ENC_  512
#define DEC_  1024
#define CONV_ 32
#define KW_   31
#define HID_  256
#define PAD_  15
#define NSPLIT_ 8

// -------- scratch (static device globals; no allocation) --------
static __device__ float g_convp[(size_t)B_ * T_ * CONV_];   // (B,T,CONV) 16 MB
static __device__ float g_decp[B_ * HID_];                  // dec proj + b_enc
static __device__ float g_energy[B_ * T_];
static __device__ float g_part[B_ * NSPLIT_ * ENC_];        // att_c partials

// ================= K0: dec_proj[b,h] = dec_state[b,:] @ W_dec[h,:] + b_enc[h]
__global__ void k_decproj(const float* __restrict__ dec_state,
                          const float* __restrict__ W_dec,
                          const float* __restrict__ b_enc) {
    __shared__ float sdec[DEC_];
    int b = blockIdx.x;
    int tid = threadIdx.x;
    for (int i = tid; i < DEC_; i += 256) sdec[i] = dec_state[b * DEC_ + i];
    __syncthreads();
    int h = tid;  // 256 threads == HID
    const float* wr = W_dec + (size_t)h * DEC_;
    float acc = b_enc[h];
#pragma unroll 4
    for (int d = 0; d < DEC_; d += 4) {
        float4 w4 = *(const float4*)(wr + d);
        acc += sdec[d] * w4.x + sdec[d + 1] * w4.y + sdec[d + 2] * w4.z + sdec[d + 3] * w4.w;
    }
    g_decp[b * HID_ + h] = acc;
}

// ================= K1: location conv: convp[b,t,c] = sum_k prev[b,t-15+k]*cw[c,k]
__global__ void k_conv(const float* __restrict__ prev,
                       const float* __restrict__ cw) {
    __shared__ float sprev[128 + KW_ - 1];  // 158
    __shared__ float scw[CONV_ * KW_];      // 992
    int b = blockIdx.y;
    int t0 = blockIdx.x * 128;
    int tid = threadIdx.x;  // 128 threads
    for (int i = tid; i < 128 + KW_ - 1; i += 128) {
        int g = t0 - PAD_ + i;
        sprev[i] = (g >= 0 && g < T_) ? prev[b * T_ + g] : 0.0f;
    }
    for (int i = tid; i < CONV_ * KW_; i += 128) scw[i] = cw[i];
    __syncthreads();
    float* outp = g_convp + ((size_t)(b * T_ + t0 + tid)) * CONV_;
#pragma unroll 4
    for (int c = 0; c < CONV_; c++) {
        float acc = 0.0f;
        const float* w = scw + c * KW_;
#pragma unroll
        for (int k = 0; k < KW_; k++) acc += sprev[tid + k] * w[k];
        outp[c] = acc;
    }
}

// ================= K2: fused energy GEMM
// energy[b,t] = w_b + sum_h w_w[h]*tanh( enc[b,t,:]@W_enc[h,:] + convp[b,t,:]@W_att[h,:] + decp[b,h] )
__global__ __launch_bounds__(256, 2)
void k_energy(const float* __restrict__ enc,
              const float* __restrict__ W_enc,
              const float* __restrict__ W_att,
              const float* __restrict__ w_w,
              const float* __restrict__ w_b) {
    __shared__ float sA[64][17];   // 64 rows x 16 k (padded)
    __shared__ float sB[256][17];  // 256 cols x 16 k (padded)

    int tile = blockIdx.x;          // 2048 tiles
    int b = tile >> 5;              // /32
    int t0 = (tile & 31) << 6;      // *64
    int tid = threadIdx.x;
    int tx = tid & 15;              // col group
    int ty = tid >> 4;              // row group

    float acc[4][16];
#pragma unroll
    for (int i = 0; i < 4; i++)
#pragma unroll
        for (int j = 0; j < 16; j++) acc[i][j] = 0.0f;

    // ---- main GEMM over ENC (K=512, chunks of 16) ----
    const int row_ld = tid >> 2;          // 0..63
    const int kq_ld = (tid & 3) * 4;      // 0,4,8,12
    const float* enc_row = enc + ((size_t)(b * T_ + t0 + row_ld)) * ENC_ + kq_ld;
    const float* w_row = W_enc + (size_t)tid * ENC_;

    for (int it = 0; it < ENC_ / 16; it++) {
        {
            float4 av = *(const float4*)(enc_row + it * 16);
            sA[row_ld][kq_ld + 0] = av.x; sA[row_ld][kq_ld + 1] = av.y;
            sA[row_ld][kq_ld + 2] = av.z; sA[row_ld][kq_ld + 3] = av.w;
#pragma unroll
            for (int q = 0; q < 4; q++) {
                float4 wv = *(const float4*)(w_row + it * 16 + q * 4);
                sB[tid][q * 4 + 0] = wv.x; sB[tid][q * 4 + 1] = wv.y;
                sB[tid][q * 4 + 2] = wv.z; sB[tid][q * 4 + 3] = wv.w;
            }
        }
        __syncthreads();
#pragma unroll
        for (int k = 0; k < 16; k++) {
            float a[4], bb[16];
#pragma unroll
            for (int i = 0; i < 4; i++) a[i] = sA[ty + 16 * i][k];
#pragma unroll
            for (int j = 0; j < 16; j++) bb[j] = sB[tx + 16 * j][k];
#pragma unroll
            for (int i = 0; i < 4; i++)
#pragma unroll
                for (int j = 0; j < 16; j++) acc[i][j] += a[i] * bb[j];
        }
        __syncthreads();
    }

    // ---- location-conv projection: 2 more chunks of 16 over CONV=32 ----
    for (int cc0 = 0; cc0 < CONV_; cc0 += 16) {
        {
            float4 cv = *(const float4*)(g_convp + ((size_t)(b * T_ + t0 + row_ld)) * CONV_ + cc0 + kq_ld);
            sA[row_ld][kq_ld + 0] = cv.x; sA[row_ld][kq_ld + 1] = cv.y;
            sA[row_ld][kq_ld + 2] = cv.z; sA[row_ld][kq_ld + 3] = cv.w;
#pragma unroll
            for (int q = 0; q < 4; q++) {
                float4 wv = *(const float4*)(W_att + (size_t)tid * CONV_ + cc0 + q * 4);
                sB[tid][q * 4 + 0] = wv.x; sB[tid][q * 4 + 1] = wv.y;
                sB[tid][q * 4 + 2] = wv.z; sB[tid][q * 4 + 3] = wv.w;
            }
        }
        __syncthreads();
#pragma unroll
        for (int k = 0; k < 16; k++) {
            float a[4], bb[16];
#pragma unroll
            for (int i = 0; i < 4; i++) a[i] = sA[ty + 16 * i][k];
#pragma unroll
            for (int j = 0; j < 16; j++) bb[j] = sB[tx + 16 * j][k];
#pragma unroll
            for (int i = 0; i < 4; i++)
#pragma unroll
                for (int j = 0; j < 16; j++) acc[i][j] += a[i] * bb[j];
        }
        __syncthreads();
    }

    // ---- epilogue: + dec, tanh, dot with w_w, row-reduce ----
    float decv[16], wv[16];
#pragma unroll
    for (int j = 0; j < 16; j++) {
        decv[j] = g_decp[b * HID_ + tx + 16 * j];
        wv[j] = w_w[tx + 16 * j];
    }
    float wb = w_b[0];
#pragma unroll
    for (int i = 0; i < 4; i++) {
        float e = 0.0f;
#pragma unroll
        for (int j = 0; j < 16; j++) e += tanhf(acc[i][j] + decv[j]) * wv[j];
        // reduce across the 16 tx lanes (stays within 16-lane halves of a warp)
        e += __shfl_xor_sync(0xffffffffu, e, 8);
        e += __shfl_xor_sync(0xffffffffu, e, 4);
        e += __shfl_xor_sync(0xffffffffu, e, 2);
        e += __shfl_xor_sync(0xffffffffu, e, 1);
        if (tx == 0) g_energy[b * T_ + t0 + ty + 16 * i] = e + wb;
    }
}

// ================= K3: masked softmax over T per batch row -> att_w into out
__global__ void k_softmax(const int* __restrict__ text_len,
                          float* __restrict__ out_attw) {
    __shared__ float sred[32];
    int b = blockIdx.x;
    int tid = threadIdx.x;  // 256
    int len = text_len[b];
    float vals[8];
    float m = -INFINITY;
#pragma unroll
    for (int p = 0; p < 8; p++) {
        int t = tid + 256 * p;
        float e = g_energy[b * T_ + t];
        vals[p] = e;
        if (t < len) m = fmaxf(m, e);
    }
    // block-reduce max
    for (int o = 16; o > 0; o >>= 1) m = fmaxf(m, __shfl_xor_sync(0xffffffffu, m, o));
    if ((tid & 31) == 0) sred[tid >> 5] = m;
    __syncthreads();
    if (tid < 32) {
        float v = (tid < 8) ? sred[tid] : -INFINITY;
        for (int o = 4; o > 0; o >>= 1) v = fmaxf(v, __shfl_xor_sync(0xffffffffu, v, o));
        if (tid == 0) sred[0] = v;
    }
    __syncthreads();
    m = sred[0];
    __syncthreads();

    float s = 0.0f;
#pragma unroll
    for (int p = 0; p < 8; p++) {
        int t = tid + 256 * p;
        float v = (t < len) ? expf(vals[p] - m) : 0.0f;
        vals[p] = v;
        s += v;
    }
    for (int o = 16; o > 0; o >>= 1) s += __shfl_xor_sync(0xffffffffu, s, o);
    if ((tid & 31) == 0) sred[tid >> 5] = s;
    __syncthreads();
    if (tid < 32) {
        float v = (tid < 8) ? sred[tid] : 0.0f;
        for (int o = 4; o > 0; o >>= 1) v += __shfl_xor_sync(0xffffffffu, v, o);
        if (tid == 0) sred[0] = v;
    }
    __syncthreads();
    float inv = 1.0f / sred[0];
#pragma unroll
    for (int p = 0; p < 8; p++) {
        int t = tid + 256 * p;
        out_attw[b * T_ + t] = vals[p] * inv;
    }
}

// ================= K4: att_c partials: split T into NSPLIT chunks
__global__ void k_attc_part(const float* __restrict__ enc,
                            const float* __restrict__ attw) {
    __shared__ float sw[256];
    int b = blockIdx.z;
    int split = blockIdx.y;
    int c = blockIdx.x * 256 + threadIdx.x;
    int t0 = split * 256;
    sw[threadIdx.x] = attw[b * T_ + t0 + threadIdx.x];
    __syncthreads();
    const float* base = enc + ((size_t)(b * T_ + t0)) * ENC_ + c;
    float acc = 0.0f;
#pragma unroll 4
    for (int t = 0; t < 256; t++) acc += base[(size_t)t * ENC_] * sw[t];
    g_part[(b * NSPLIT_ + split) * ENC_ + c] = acc;
}

// ================= K5: reduce partials -> att_c
__global__ void k_attc_reduce(float* __restrict__ out_attc) {
    int idx = blockIdx.x * 256 + threadIdx.x;  // B*ENC threads
    int b = idx / ENC_;
    int c = idx % ENC_;
    float s = 0.0f;
#pragma unroll
    for (int p = 0; p < NSPLIT_; p++) s += g_part[(b * NSPLIT_ + p) * ENC_ + c];
    out_attc[idx] = s;
}

// ================= launcher =================
extern "C" void kernel_launch(void* const* d_in, const int* in_sizes, int n_in,
                              void* d_out, int out_size) {
    const float* enc      = (const float*)d_in[0];   // (B,T,ENC)
    const float* dec_st   = (const float*)d_in[1];   // (B,DEC)
    const float* prev     = (const float*)d_in[2];   // (B,T)
    const int*   text_len = (const int*)  d_in[3];   // (B,)
    const float* W_enc    = (const float*)d_in[4];   // (HID,ENC)
    const float* b_enc    = (const float*)d_in[5];   // (HID,)
    const float* W_dec    = (const float*)d_in[6];   // (HID,DEC)
    const float* W_att    = (const float*)d_in[7];   // (HID,CONV)
    const float* conv_w   = (const float*)d_in[8];   // (CONV,1,K)
    const float* w_w      = (const float*)d_in[9];   // (1,HID)
    const float* w_b      = (const float*)d_in[10];  // (1,)

    float* out_attc = (float*)d_out;                 // B*ENC
    float* out_attw = (float*)d_out + (size_t)B_ * ENC_;  // B*T

    k_decproj<<<B_, 256>>>(dec_st, W_dec, b_enc);
    {
        dim3 g(T_ / 128, B_);
        k_conv<<<g, 128>>>(prev, conv_w);
    }
    k_energy<<<B_ * (T_ / 64), 256>>>(enc, W_enc, W_att, w_w, w_b);
    k_softmax<<<B_, 256>>>(text_len, out_attw);
    {
        dim3 g(ENC_ / 256, NSPLIT_, B_);
        k_attc_part<<<g, 256>>>(enc, out_attw);
    }
    k_attc_reduce<<<(B_ * ENC_) / 256, 256>>>(out_attc);
}